// round 13
// baseline (speedup 1.0000x reference)
#include <cuda_runtime.h>
#include <cuda_bf16.h>
#include <cstdint>

#define Bn 1024
#define Sn 128
#define Dn 768
#define Cn 56
#define KC 16
#define NCHUNK 48
#define NBUF 6
#define DIST 5
#define WBUF (16 * KC)                 /* floats per warp-buffer = 256 (1KB) */
#define A_BYTES (8 * NBUF * WBUF * 4)  /* 49152 */
#define SMEM_DYN (A_BYTES)

// Fragment-major packed weights: Wp[ci][j][lane] = uint2 B-fragment for
// mma j at chunk ci. lane=(g<<2)|t4, c=8j+g, k0=16ci+4t4:
//   .x = bf16x2(W[c][k0],W[c][k0+1]), .y = bf16x2(W[c][k0+2],W[c][k0+3])
// One warp's (ci,j) read = 32 lanes x 8B = 256B contiguous (2 lines, coalesced).
__device__ uint2 g_Wp[NCHUNK * 7 * 32];

__device__ __forceinline__ float wval(const float* w2, const float* w3,
                                      const float* w4, const float* w5,
                                      int c, int d) {
    if (c < 8)       { int f = c / 2;        int j = c % 2;        return w2[(f * Dn + d) * 2 + j]; }
    else if (c < 20) { int cc = c - 8;  int f = cc / 3; int j = cc % 3; return w3[(f * Dn + d) * 3 + j]; }
    else if (c < 36) { int cc = c - 20; int f = cc / 4; int j = cc % 4; return w4[(f * Dn + d) * 4 + j]; }
    else             { int cc = c - 36; int f = cc / 5; int j = cc % 5; return w5[(f * Dn + d) * 5 + j]; }
}

__device__ __forceinline__ uint32_t f2bf2(float lo, float hi) {
    __nv_bfloat162 h = __float22bfloat162_rn(make_float2(lo, hi));
    return *reinterpret_cast<uint32_t*>(&h);
}

__global__ void build_wp_kernel(const float* __restrict__ w2, const float* __restrict__ w3,
                                const float* __restrict__ w4, const float* __restrict__ w5) {
    int i = blockIdx.x * blockDim.x + threadIdx.x;
    if (i >= NCHUNK * 7 * 32) return;
    int ci = i / 224, rem = i % 224;
    int j = rem / 32, lane = rem % 32;
    int g = lane >> 2, t4 = lane & 3;
    int c = 8 * j + g;
    int k0 = ci * KC + 4 * t4;
    uint2 v;
    v.x = f2bf2(wval(w2, w3, w4, w5, c, k0),     wval(w2, w3, w4, w5, c, k0 + 1));
    v.y = f2bf2(wval(w2, w3, w4, w5, c, k0 + 2), wval(w2, w3, w4, w5, c, k0 + 3));
    g_Wp[i] = v;
}

__device__ __forceinline__ void cp16(uint32_t dst_smem, const void* src) {
    asm volatile("cp.async.cg.shared.global [%0], [%1], 16;\n" :: "r"(dst_smem), "l"(src));
}

__global__ __launch_bounds__(256, 4) void fused_kernel(
    const int* __restrict__ x, const float* __restrict__ hidden,
    const float* __restrict__ b2, const float* __restrict__ b3,
    const float* __restrict__ b4, const float* __restrict__ b5,
    const float* __restrict__ fcw, const float* __restrict__ fcb,
    float* __restrict__ out)
{
    extern __shared__ __align__(16) unsigned char sraw[];
    float* As = reinterpret_cast<float*>(sraw);                       // [8 warps][NBUF][16][16]
    float (*Psm)[Cn + 1] = reinterpret_cast<float (*)[Cn + 1]>(sraw); // epilogue reuse (29.2KB < 48KB)

    __shared__ int order[Sn];
    __shared__ unsigned mask4[4];
    __shared__ int sh_len;
    __shared__ float feats[16];

    const int b    = blockIdx.x;
    const int tid  = threadIdx.x;
    const int warp = tid >> 5;
    const int lane = tid & 31;
    const int g    = lane >> 2;   // 0..7
    const int t4   = lane & 3;    // 0..3

    const float* hidb = hidden + (long)b * Sn * Dn;

    // ---- warp-local A staging: warp owns rows [16warp, 16warp+16), 2x16B per lane ----
    const int u0r = lane >> 2, u0q = lane & 3;
    const uint32_t wbase = (uint32_t)__cvta_generic_to_shared(As + warp * NBUF * WBUF);
    const uint32_t a_d0 = (uint32_t)(u0r * KC + 4 * u0q) * 4;          // rows 0..7  (= lane*16B)
    const uint32_t a_d1 = a_d0 + (uint32_t)(8 * KC) * 4;               // rows 8..15
    const float* a_s0 = hidb + (long)(warp * 16 + u0r) * Dn + 4 * u0q;
    const float* a_s1 = a_s0 + 8L * Dn;

    auto issueA = [&](int ci, int buf) {
        const uint32_t bb = wbase + (uint32_t)(buf * WBUF * 4);
        cp16(bb + a_d0, a_s0 + ci * KC);
        cp16(bb + a_d1, a_s1 + ci * KC);
        asm volatile("cp.async.commit_group;\n");
    };

    issueA(0, 0); issueA(1, 1); issueA(2, 2); issueA(3, 3); issueA(4, 4);

    // ---- stable compaction order (overlaps with first loads) ----
    if (tid < Sn) {
        int nz = (x[b * Sn + tid] != 0);
        unsigned m = __ballot_sync(0xFFFFFFFFu, nz);
        if (lane == 0) mask4[warp] = m;
    }
    __syncthreads();
    if (tid < Sn) {
        unsigned mw = mask4[warp];
        int nzbefore = __popc(mw & ((1u << lane) - 1u));
        int nztot_before = 0, total = 0;
        #pragma unroll
        for (int w = 0; w < 4; w++) { if (w < warp) nztot_before += __popc(mask4[w]); total += __popc(mask4[w]); }
        int isnz = (mw >> lane) & 1;
        int pos = isnz ? (nztot_before + nzbefore)
                       : (total + (tid - nztot_before - nzbefore));
        order[pos] = tid;
        if (tid == 0) sh_len = total;
    }
    __syncthreads();   // last CTA-wide sync before barrier-free mainloop

    // ---- barrier-free GEMM mainloop ----
    float acc[7][4];
    #pragma unroll
    for (int j = 0; j < 7; j++)
        #pragma unroll
        for (int q = 0; q < 4; q++) acc[j][q] = 0.0f;

    const float* Awarp = As + warp * NBUF * WBUF;
    const uint32_t a_off0 = (uint32_t)(g * KC + 4 * t4);
    const uint32_t a_off1 = a_off0 + 8 * KC;
    const uint2* wp_lane = g_Wp + lane;       // + (ci*7 + j)*32

    auto computeChunk = [&](int buf, int ci) {
        const float* Abuf = Awarp + buf * WBUF;
        float4 f0 = *(const float4*)(Abuf + a_off0);
        float4 f1 = *(const float4*)(Abuf + a_off1);
        uint32_t a0 = f2bf2(f0.x, f0.y), a2 = f2bf2(f0.z, f0.w);
        uint32_t a1 = f2bf2(f1.x, f1.y), a3 = f2bf2(f1.z, f1.w);
        const uint2* wp = wp_lane + (ci * 7) * 32;
        #pragma unroll
        for (int j = 0; j < 7; j++) {
            uint2 bb = __ldg(wp + j * 32);
            asm volatile(
                "mma.sync.aligned.m16n8k16.row.col.f32.bf16.bf16.f32 "
                "{%0,%1,%2,%3}, {%4,%5,%6,%7}, {%8,%9}, {%0,%1,%2,%3};\n"
                : "+f"(acc[j][0]), "+f"(acc[j][1]), "+f"(acc[j][2]), "+f"(acc[j][3])
                : "r"(a0), "r"(a1), "r"(a2), "r"(a3), "r"(bb.x), "r"(bb.y));
        }
    };

    int buf = 0, bufN = DIST;
    #pragma unroll 1
    for (int ci = 0; ci < NCHUNK - DIST; ci++) {
        asm volatile("cp.async.wait_group 4;\n" ::: "memory");
        __syncwarp();
        issueA(ci + DIST, bufN);
        computeChunk(buf, ci);
        if (++buf == NBUF) buf = 0;
        if (++bufN == NBUF) bufN = 0;
    }
    // tail: chunks 43..47, buffers (43%6)=1,2,3,4,5
    asm volatile("cp.async.wait_group 4;\n" ::: "memory");
    __syncwarp(); computeChunk(1, 43);
    asm volatile("cp.async.wait_group 3;\n" ::: "memory");
    __syncwarp(); computeChunk(2, 44);
    asm volatile("cp.async.wait_group 2;\n" ::: "memory");
    __syncwarp(); computeChunk(3, 45);
    asm volatile("cp.async.wait_group 1;\n" ::: "memory");
    __syncwarp(); computeChunk(4, 46);
    asm volatile("cp.async.wait_group 0;\n" ::: "memory");
    __syncwarp(); computeChunk(5, 47);

    // ---- all warps done with As before Psm overwrites it ----
    __syncthreads();
    const int rowA = warp * 16 + g;
    #pragma unroll
    for (int j = 0; j < 7; j++) {
        int c = j * 8 + 2 * t4;
        Psm[rowA][c]         = acc[j][0];
        Psm[rowA][c + 1]     = acc[j][1];
        Psm[rowA + 8][c]     = acc[j][2];
        Psm[rowA + 8][c + 1] = acc[j][3];
    }
    __syncthreads();

    // ---- ragged conv + max-pool: 16 features, 2 per warp ----
    const int L = sh_len;
    #pragma unroll
    for (int r = 0; r < 2; r++) {
        int fi = warp + r * 8;
        int kk = fi / 4 + 2;
        int f  = fi % 4;
        int cb = (kk == 2 ? 0 : (kk == 3 ? 8 : (kk == 4 ? 20 : 36))) + f * kk;
        const float* bptr = (kk == 2 ? b2 : (kk == 3 ? b3 : (kk == 4 ? b4 : b5)));
        float bias = bptr[f];
        int nt = L - kk + 1;
        float m = -1e30f;
        for (int tp = lane; tp < nt; tp += 32) {
            float sconv = bias;
            for (int j = 0; j < kk; j++)
                sconv += Psm[order[tp + j]][cb + j];
            m = fmaxf(m, sconv);
        }
        #pragma unroll
        for (int off = 16; off; off >>= 1)
            m = fmaxf(m, __shfl_xor_sync(0xFFFFFFFFu, m, off));
        if (lane == 0) feats[fi] = m;
    }
    __syncthreads();

    if (tid == 0) {
        float z = fcb[0];
        #pragma unroll
        for (int i = 0; i < 16; i++) z += feats[i] * fcw[i];
        out[b] = 1.0f / (1.0f + expf(-z));
    }
}

extern "C" void kernel_launch(void* const* d_in, const int* in_sizes, int n_in,
                              void* d_out, int out_size) {
    const int*   x      = (const int*)d_in[0];
    const float* hidden = (const float*)d_in[1];
    const float* w2     = (const float*)d_in[2];
    const float* b2     = (const float*)d_in[3];
    const float* w3     = (const float*)d_in[4];
    const float* b3     = (const float*)d_in[5];
    const float* w4     = (const float*)d_in[6];
    const float* b4     = (const float*)d_in[7];
    const float* w5     = (const float*)d_in[8];
    const float* b5     = (const float*)d_in[9];
    const float* fcw    = (const float*)d_in[10];
    const float* fcb    = (const float*)d_in[11];
    float* out = (float*)d_out;

    cudaFuncSetAttribute(fused_kernel, cudaFuncAttributeMaxDynamicSharedMemorySize, SMEM_DYN);

    build_wp_kernel<<<(NCHUNK * 7 * 32 + 255) / 256, 256>>>(w2, w3, w4, w5);
    fused_kernel<<<Bn, 256, SMEM_DYN>>>(x, hidden, b2, b3, b4, b5, fcw, fcb, out);
}